// round 5
// baseline (speedup 1.0000x reference)
#include <cuda_runtime.h>
#include <cstdint>

#define HID   128
#define NEDGE 800000
#define NNODE 50000
#define NTILE 6250          // NEDGE / 128
#define GRID_TC 148
#define EB_STRIDE 140       // words per edge row (stride % 32 == 12 -> conflict-free)

// ---- scratch (static __device__ arrays; allocation-free) ----
__device__ float g_Ha[NNODE * HID];
__device__ float g_Hb[NNODE * HID];
__device__ float g_a[NEDGE];
__device__ int   g_row[NEDGE];
__device__ int   g_col[NEDGE];
__device__ int   g_is64;
__device__ float g_pm[256];
__device__ float g_ps[256];
__device__ float g_stats[2];

// ---- helpers ----
__device__ __forceinline__ uint32_t f2tf32(float x) {
    uint32_t u;
    asm("cvt.rna.tf32.f32 %0, %1;" : "=r"(u) : "f"(x));
    return u;
}
__device__ __forceinline__ void mma_tf(float* c, const uint32_t* a, uint32_t b0, uint32_t b1) {
    asm volatile(
        "mma.sync.aligned.m16n8k8.row.col.f32.tf32.tf32.f32 "
        "{%0,%1,%2,%3}, {%4,%5,%6,%7}, {%8,%9}, {%0,%1,%2,%3};"
        : "+f"(c[0]), "+f"(c[1]), "+f"(c[2]), "+f"(c[3])
        : "r"(a[0]), "r"(a[1]), "r"(a[2]), "r"(a[3]), "r"(b0), "r"(b1));
}
__device__ __forceinline__ float elu(float x) {
    return x > 0.f ? x : (__expf(x) - 1.f);
}

// ---- packed f32x2 helpers for the node GEMM ----
__device__ __forceinline__ unsigned long long pk(float x, float y) {
    unsigned long long r;
    asm("mov.b64 %0, {%1, %2};" : "=l"(r) : "f"(x), "f"(y));
    return r;
}
__device__ __forceinline__ unsigned long long pk1(float x) { return pk(x, x); }
__device__ __forceinline__ void fma2(unsigned long long& d, unsigned long long a, unsigned long long b) {
    asm("fma.rn.f32x2 %0, %1, %2, %0;" : "+l"(d) : "l"(a), "l"(b));
}
__device__ __forceinline__ float2 upk(unsigned long long v) {
    float2 r;
    asm("mov.b64 {%0, %1}, %2;" : "=f"(r.x), "=f"(r.y) : "l"(v));
    return r;
}

// ============================================================
// Kernel 0a/0b: edge_index dtype detect + convert
// ============================================================
__global__ void detect(const int* __restrict__ ei32) {
    if (threadIdx.x == 0 && blockIdx.x == 0) {
        int orv = 0;
        for (int i = 0; i < 64; i++) orv |= ei32[2 * i + 1];
        g_is64 = (orv == 0) ? 1 : 0;
    }
}
__global__ void __launch_bounds__(256) convert(const void* __restrict__ eiraw) {
    int e = blockIdx.x * 256 + threadIdx.x;
    if (e >= NEDGE) return;
    int row, col;
    if (g_is64) {
        const long long* p = (const long long*)eiraw;
        row = (int)p[e]; col = (int)p[NEDGE + e];
    } else {
        const int* p = (const int*)eiraw;
        row = p[e]; col = p[NEDGE + e];
    }
    g_row[e] = min(max(row, 0), NNODE - 1);
    g_col[e] = min(max(col, 0), NNODE - 1);
}

// ============================================================
// Kernel 1: node GEMM  Ha = h@Wa, Hb = h@Wb  (FFMA2, unchanged)
// ============================================================
__global__ void __launch_bounds__(256, 1) node_gemm(const float* __restrict__ h,
                                                    const float* __restrict__ W1) {
    extern __shared__ char smraw[];
    unsigned long long* wab = (unsigned long long*)smraw;
    float* hst = (float*)(smraw + 131072);

    int tid = threadIdx.x;
    for (int idx = tid; idx < 128 * 128; idx += 256) {
        int k = idx >> 7, p = idx & 127;
        const float* src = (p < 64) ? &W1[k * HID + 2 * p]
                                    : &W1[(HID + k) * HID + 2 * (p - 64)];
        float2 v = *(const float2*)src;
        wab[idx] = pk(v.x, v.y);
    }
    __syncthreads();

    int w = tid >> 5, l = tid & 31;
    int group = blockIdx.x * 8 + w;
    if (group * 4 >= NNODE) return;
    int n0 = group * 4;

    float* hw = hst + w * 4 * HID;
#pragma unroll
    for (int e = 0; e < 4; e++) {
        float4 v = *(const float4*)&h[(size_t)(n0 + e) * HID + 4 * l];
        *(float4*)&hw[e * HID + 4 * l] = v;
    }
    __syncwarp();

    unsigned long long acc[4][4];
#pragma unroll
    for (int e = 0; e < 4; e++)
#pragma unroll
        for (int j = 0; j < 4; j++) acc[e][j] = 0ULL;

    for (int k = 0; k < HID; k += 2) {
        unsigned long long w0[4], w1[4];
#pragma unroll
        for (int j = 0; j < 4; j++) {
            w0[j] = wab[k * 128 + l + 32 * j];
            w1[j] = wab[(k + 1) * 128 + l + 32 * j];
        }
#pragma unroll
        for (int e = 0; e < 4; e++) {
            float2 hv = *(float2*)&hw[e * HID + k];
            unsigned long long hx = pk1(hv.x), hy = pk1(hv.y);
#pragma unroll
            for (int j = 0; j < 4; j++) {
                fma2(acc[e][j], hx, w0[j]);
                fma2(acc[e][j], hy, w1[j]);
            }
        }
    }

#pragma unroll
    for (int e = 0; e < 4; e++)
#pragma unroll
        for (int j = 0; j < 4; j++) {
            int p = l + 32 * j;
            float2 v = upk(acc[e][j]);
            if (p < 64)
                *(float2*)&g_Ha[(size_t)(n0 + e) * HID + 2 * p] = v;
            else
                *(float2*)&g_Hb[(size_t)(n0 + e) * HID + 2 * (p - 64)] = v;
        }
}

// ============================================================
// Kernel 2: edge GEMM via mma.sync tf32 + fused epilogue
//   persistent 148 CTAs, 384 threads:
//   warps 0-7 compute (warp w owns output dims [16w,16w+16))
//   warps 8-11 load next tile (LDG->cvt.tf32->permuted STS) + finalize prev
// ============================================================
// loader: fill one edge tile (tl in [0,128))
__device__ __forceinline__ void load_tile(uint32_t* eb, int* idx,
                                          const float* __restrict__ ea,
                                          int tile, int tl) {
    idx[tl]       = g_row[tile * 128 + tl];
    idx[128 + tl] = g_col[tile * 128 + tl];
    int rbase = tl >> 2, cbase = tl & 3;
#pragma unroll
    for (int i = 0; i < 4; i++) {
        int row = rbase + 32 * i;
        const float4* src = (const float4*)(ea + ((size_t)tile * 128 + row) * HID);
        uint32_t* drow = eb + row * EB_STRIDE;
#pragma unroll
        for (int j = 0; j < 4; j++) {
            int kb = cbase + 4 * j;               // k-block of 8 floats
            float4 v0 = src[kb * 2];
            float4 v1 = src[kb * 2 + 1];
            uint4 o0, o1;                          // pair-permute (k, k+4)
            o0.x = f2tf32(v0.x); o0.y = f2tf32(v1.x);
            o0.z = f2tf32(v0.y); o0.w = f2tf32(v1.y);
            o1.x = f2tf32(v0.z); o1.y = f2tf32(v1.z);
            o1.z = f2tf32(v0.w); o1.w = f2tf32(v1.w);
            *(uint4*)(drow + kb * 8)     = o0;
            *(uint4*)(drow + kb * 8 + 4) = o1;
        }
    }
}

__device__ __forceinline__ void finalize(const float* part, int tile, int tl, float b2v) {
    float s = 0.f;
#pragma unroll
    for (int w = 0; w < 8; w++) s += part[w * 128 + tl];
    float a = s + b2v;
    g_a[tile * 128 + tl] = a > 0.f ? a : 0.2f * a;
}

__global__ void __launch_bounds__(384, 1) edge_mma(const float* __restrict__ ea,
                                                   const float* __restrict__ W1,
                                                   const float* __restrict__ b1,
                                                   const float* __restrict__ W2,
                                                   const float* __restrict__ b2) {
    extern __shared__ char sm[];
    uint32_t* eb0   = (uint32_t*)sm;                  // 71680 B
    uint32_t* eb1   = (uint32_t*)(sm + 71680);        // 71680 B
    float*    part0 = (float*)(sm + 143360);          // 4096 B
    float*    part1 = (float*)(sm + 147456);          // 4096 B
    int*      idx0  = (int*)(sm + 151552);            // 1024 B
    int*      idx1  = (int*)(sm + 152576);            // 1024 B
    float*    b1s   = (float*)(sm + 153600);          // 512 B
    float*    w2s   = (float*)(sm + 154112);          // 512 B

    int tid = threadIdx.x, wid = tid >> 5, lane = tid & 31;
    int tg = lane >> 2, tk = lane & 3;                // mma groupID / thread-in-group
    int bid = blockIdx.x;
    float b2v = b2[0];

    if (tid < 128) { b1s[tid] = b1[tid]; w2s[tid] = W2[tid]; }

    // A fragments: Wc^T slab for this warp (compute warps only), once per kernel
    uint32_t afr[16][4];
    if (wid < 8) {
        int o0 = 16 * wid + tg;
#pragma unroll
        for (int K8 = 0; K8 < 16; K8++) {
            int kb = 2 * HID + K8 * 8;
            afr[K8][0] = f2tf32(W1[(kb + tk) * HID + o0]);
            afr[K8][1] = f2tf32(W1[(kb + tk) * HID + o0 + 8]);
            afr[K8][2] = f2tf32(W1[(kb + tk + 4) * HID + o0]);
            afr[K8][3] = f2tf32(W1[(kb + tk + 4) * HID + o0 + 8]);
        }
    } else {
        load_tile(eb0, idx0, ea, bid, tid - 256);
    }
    __syncthreads();

    int it = 0;
    for (int tile = bid; tile < NTILE; tile += GRID_TC, it++) {
        int p = it & 1;
        uint32_t* ebc = p ? eb1 : eb0;
        float*    ptc = p ? part1 : part0;
        int*      idc = p ? idx1 : idx0;

        if (wid < 8) {
            int o0 = 16 * wid + tg, o1 = o0 + 8;
            float w2a = w2s[o0], w2b = w2s[o1];
            float b1a = b1s[o0], b1b = b1s[o1];
#pragma unroll
            for (int slab = 0; slab < 2; slab++) {
                float c[8][4];
#pragma unroll
                for (int g = 0; g < 8; g++) { c[g][0]=0.f; c[g][1]=0.f; c[g][2]=0.f; c[g][3]=0.f; }
                const uint32_t* ebp = ebc + slab * 64 * EB_STRIDE;
#pragma unroll
                for (int K8 = 0; K8 < 16; K8++) {
#pragma unroll
                    for (int g = 0; g < 8; g++) {
                        uint2 b = *(const uint2*)(ebp + (g * 8 + tg) * EB_STRIDE + K8 * 8 + 2 * tk);
                        mma_tf(c[g], afr[K8], b.x, b.y);
                    }
                }
                // fused epilogue
#pragma unroll
                for (int g = 0; g < 8; g++) {
                    int el = slab * 64 + g * 8 + 2 * tk;
                    int r0 = idc[el],     q0 = idc[128 + el];
                    int r1 = idc[el + 1], q1 = idc[128 + el + 1];
                    float pre00 = c[g][0] + g_Ha[(size_t)r0 * HID + o0] + g_Hb[(size_t)q0 * HID + o0] + b1a;
                    float pre01 = c[g][1] + g_Ha[(size_t)r1 * HID + o0] + g_Hb[(size_t)q1 * HID + o0] + b1a;
                    float pre10 = c[g][2] + g_Ha[(size_t)r0 * HID + o1] + g_Hb[(size_t)q0 * HID + o1] + b1b;
                    float pre11 = c[g][3] + g_Ha[(size_t)r1 * HID + o1] + g_Hb[(size_t)q1 * HID + o1] + b1b;
                    float p0 = elu(pre00) * w2a + elu(pre10) * w2b;
                    float p1 = elu(pre01) * w2a + elu(pre11) * w2b;
#pragma unroll
                    for (int off = 4; off <= 16; off <<= 1) {
                        p0 += __shfl_xor_sync(0xffffffffu, p0, off);
                        p1 += __shfl_xor_sync(0xffffffffu, p1, off);
                    }
                    if (tg == 0)
                        *(float2*)&ptc[wid * 128 + el] = make_float2(p0, p1);
                }
            }
        } else {
            int tl = tid - 256;
            int nt = tile + GRID_TC;
            if (nt < NTILE)
                load_tile(p ? eb0 : eb1, p ? idx0 : idx1, ea, nt, tl);
            if (it > 0)
                finalize(p ? part0 : part1, tile - GRID_TC, tl, b2v);
        }
        __syncthreads();
    }
    // tail: finalize the last tile
    if (wid >= 8 && it > 0) {
        int lastp = (it - 1) & 1;
        finalize(lastp ? part1 : part0, bid + (it - 1) * GRID_TC, tid - 256, b2v);
    }
}

// ============================================================
// Kernels 3/4: deterministic two-stage online logsumexp
// ============================================================
__device__ __forceinline__ void merge_ms(float& m, float& s, float m2, float s2) {
    float mn = fmaxf(m, m2);
    s = s * __expf(m - mn) + s2 * __expf(m2 - mn);
    m = mn;
}

__global__ void softmax_part() {
    int gtid = blockIdx.x * 256 + threadIdx.x;
    float m = -1e30f, s = 0.f;
    for (int i = gtid; i < NEDGE; i += 256 * 256) {
        float v = g_a[i];
        if (v > m) { s = s * __expf(m - v) + 1.f; m = v; }
        else       { s += __expf(v - m); }
    }
    __shared__ float sm_[256], ss_[256];
    sm_[threadIdx.x] = m; ss_[threadIdx.x] = s;
    __syncthreads();
    for (int off = 128; off; off >>= 1) {
        if (threadIdx.x < off) {
            float mm = sm_[threadIdx.x], ssv = ss_[threadIdx.x];
            merge_ms(mm, ssv, sm_[threadIdx.x + off], ss_[threadIdx.x + off]);
            sm_[threadIdx.x] = mm; ss_[threadIdx.x] = ssv;
        }
        __syncthreads();
    }
    if (threadIdx.x == 0) { g_pm[blockIdx.x] = sm_[0]; g_ps[blockIdx.x] = ss_[0]; }
}

__global__ void softmax_final() {
    int t = threadIdx.x;
    __shared__ float sm_[256], ss_[256];
    sm_[t] = g_pm[t]; ss_[t] = g_ps[t];
    __syncthreads();
    for (int off = 128; off; off >>= 1) {
        if (t < off) {
            float mm = sm_[t], ssv = ss_[t];
            merge_ms(mm, ssv, sm_[t + off], ss_[t + off]);
            sm_[t] = mm; ss_[t] = ssv;
        }
        __syncthreads();
    }
    if (t == 0) { g_stats[0] = sm_[0]; g_stats[1] = 1.f / ss_[0]; }
}

// ============================================================
// Kernel 5: scatter  out[row] += alpha_e * h[col]   (red.v4.f32)
// ============================================================
__global__ void __launch_bounds__(256) scatter(const float* __restrict__ h,
                                               float* __restrict__ out) {
    int gw = (blockIdx.x * 256 + threadIdx.x) >> 5;
    int l = threadIdx.x & 31;
    float m = g_stats[0], inv = g_stats[1];
    int e0 = gw * 4;
#pragma unroll
    for (int e = 0; e < 4; e++) {
        int ed = e0 + e;
        if (ed >= NEDGE) return;
        float alpha = __expf(g_a[ed] - m) * inv;
        int row = g_row[ed];
        int col = g_col[ed];
        float4 hv = *(const float4*)&h[(size_t)col * HID + 4 * l];
        float* dst = &out[(size_t)row * HID + 4 * l];
        asm volatile("red.global.add.v4.f32 [%0], {%1, %2, %3, %4};"
                     :: "l"(dst), "f"(alpha * hv.x), "f"(alpha * hv.y),
                        "f"(alpha * hv.z), "f"(alpha * hv.w)
                     : "memory");
    }
}

// ============================================================
extern "C" void kernel_launch(void* const* d_in, const int* in_sizes, int n_in,
                              void* d_out, int out_size) {
    const float* h  = (const float*)d_in[0];
    const void*  ei = (const void*)d_in[1];
    const float* ea = (const float*)d_in[2];
    const float* W1 = (const float*)d_in[3];
    const float* b1 = (const float*)d_in[4];
    const float* W2 = (const float*)d_in[5];
    const float* b2 = (const float*)d_in[6];
    float* out = (float*)d_out;

    cudaFuncSetAttribute(node_gemm, cudaFuncAttributeMaxDynamicSharedMemorySize, 147456);
    cudaFuncSetAttribute(edge_mma,  cudaFuncAttributeMaxDynamicSharedMemorySize, 154624);

    detect<<<1, 32>>>((const int*)ei);
    convert<<<(NEDGE + 255) / 256, 256>>>(ei);
    node_gemm<<<1563, 256, 147456>>>(h, W1);
    edge_mma<<<GRID_TC, 384, 154624>>>(ea, W1, b1, W2, b2);
    softmax_part<<<256, 256>>>();
    softmax_final<<<1, 256>>>();
    cudaMemsetAsync(d_out, 0, (size_t)out_size * sizeof(float));
    scatter<<<25000, 256>>>(h, out);
}

// round 6
// speedup vs baseline: 1.6865x; 1.6865x over previous
#include <cuda_runtime.h>
#include <cstdint>

#define HID   128
#define NEDGE 800000
#define NNODE 50000
#define NTILE 6250          // NEDGE / 128
#define GRID_TC 148
#define EB_STRIDE 140       // words per edge row (stride % 32 == 12 -> conflict-free)
#define D_STRIDE  132       // D tile stride (conflict-free STS/LDS)

// ---- scratch (static __device__ arrays; allocation-free) ----
__device__ float g_Ha[NNODE * HID];
__device__ float g_Hb[NNODE * HID];
__device__ float g_a[NEDGE];
__device__ int   g_row[NEDGE];
__device__ int   g_col[NEDGE];
__device__ int   g_is64;
__device__ float g_pm[256];
__device__ float g_ps[256];
__device__ float g_stats[2];

// ---- helpers ----
__device__ __forceinline__ uint32_t f2tf32(float x) {
    uint32_t u;
    asm("cvt.rna.tf32.f32 %0, %1;" : "=r"(u) : "f"(x));
    return u;
}
__device__ __forceinline__ void mma_tf(float* c, const uint32_t* a, uint32_t b0, uint32_t b1) {
    asm volatile(
        "mma.sync.aligned.m16n8k8.row.col.f32.tf32.tf32.f32 "
        "{%0,%1,%2,%3}, {%4,%5,%6,%7}, {%8,%9}, {%0,%1,%2,%3};"
        : "+f"(c[0]), "+f"(c[1]), "+f"(c[2]), "+f"(c[3])
        : "r"(a[0]), "r"(a[1]), "r"(a[2]), "r"(a[3]), "r"(b0), "r"(b1));
}
__device__ __forceinline__ float elu(float x) {
    return x > 0.f ? x : (__expf(x) - 1.f);
}

// ---- packed f32x2 helpers for the node GEMM ----
__device__ __forceinline__ unsigned long long pk(float x, float y) {
    unsigned long long r;
    asm("mov.b64 %0, {%1, %2};" : "=l"(r) : "f"(x), "f"(y));
    return r;
}
__device__ __forceinline__ unsigned long long pk1(float x) { return pk(x, x); }
__device__ __forceinline__ void fma2(unsigned long long& d, unsigned long long a, unsigned long long b) {
    asm("fma.rn.f32x2 %0, %1, %2, %0;" : "+l"(d) : "l"(a), "l"(b));
}
__device__ __forceinline__ float2 upk(unsigned long long v) {
    float2 r;
    asm("mov.b64 {%0, %1}, %2;" : "=f"(r.x), "=f"(r.y) : "l"(v));
    return r;
}

// ============================================================
// Kernel 0a/0b: edge_index dtype detect + convert
// ============================================================
__global__ void detect(const int* __restrict__ ei32) {
    if (threadIdx.x == 0 && blockIdx.x == 0) {
        int orv = 0;
        for (int i = 0; i < 64; i++) orv |= ei32[2 * i + 1];
        g_is64 = (orv == 0) ? 1 : 0;
    }
}
__global__ void __launch_bounds__(256) convert(const void* __restrict__ eiraw) {
    int e = blockIdx.x * 256 + threadIdx.x;
    if (e >= NEDGE) return;
    int row, col;
    if (g_is64) {
        const long long* p = (const long long*)eiraw;
        row = (int)p[e]; col = (int)p[NEDGE + e];
    } else {
        const int* p = (const int*)eiraw;
        row = p[e]; col = p[NEDGE + e];
    }
    g_row[e] = min(max(row, 0), NNODE - 1);
    g_col[e] = min(max(col, 0), NNODE - 1);
}

// ============================================================
// Kernel 1: node GEMM  Ha = h@Wa, Hb = h@Wb  (FFMA2, unchanged)
// ============================================================
__global__ void __launch_bounds__(256, 1) node_gemm(const float* __restrict__ h,
                                                    const float* __restrict__ W1) {
    extern __shared__ char smraw[];
    unsigned long long* wab = (unsigned long long*)smraw;
    float* hst = (float*)(smraw + 131072);

    int tid = threadIdx.x;
    for (int idx = tid; idx < 128 * 128; idx += 256) {
        int k = idx >> 7, p = idx & 127;
        const float* src = (p < 64) ? &W1[k * HID + 2 * p]
                                    : &W1[(HID + k) * HID + 2 * (p - 64)];
        float2 v = *(const float2*)src;
        wab[idx] = pk(v.x, v.y);
    }
    __syncthreads();

    int w = tid >> 5, l = tid & 31;
    int group = blockIdx.x * 8 + w;
    if (group * 4 >= NNODE) return;
    int n0 = group * 4;

    float* hw = hst + w * 4 * HID;
#pragma unroll
    for (int e = 0; e < 4; e++) {
        float4 v = *(const float4*)&h[(size_t)(n0 + e) * HID + 4 * l];
        *(float4*)&hw[e * HID + 4 * l] = v;
    }
    __syncwarp();

    unsigned long long acc[4][4];
#pragma unroll
    for (int e = 0; e < 4; e++)
#pragma unroll
        for (int j = 0; j < 4; j++) acc[e][j] = 0ULL;

    for (int k = 0; k < HID; k += 2) {
        unsigned long long w0[4], w1[4];
#pragma unroll
        for (int j = 0; j < 4; j++) {
            w0[j] = wab[k * 128 + l + 32 * j];
            w1[j] = wab[(k + 1) * 128 + l + 32 * j];
        }
#pragma unroll
        for (int e = 0; e < 4; e++) {
            float2 hv = *(float2*)&hw[e * HID + k];
            unsigned long long hx = pk1(hv.x), hy = pk1(hv.y);
#pragma unroll
            for (int j = 0; j < 4; j++) {
                fma2(acc[e][j], hx, w0[j]);
                fma2(acc[e][j], hy, w1[j]);
            }
        }
    }

#pragma unroll
    for (int e = 0; e < 4; e++)
#pragma unroll
        for (int j = 0; j < 4; j++) {
            int p = l + 32 * j;
            float2 v = upk(acc[e][j]);
            if (p < 64)
                *(float2*)&g_Ha[(size_t)(n0 + e) * HID + 2 * p] = v;
            else
                *(float2*)&g_Hb[(size_t)(n0 + e) * HID + 2 * (p - 64)] = v;
        }
}

// ============================================================
// Kernel 2: edge GEMM via mma.sync tf32 + coalesced epilogue
//   persistent 148 CTAs, 384 threads, per tile:
//   phase A: warps 0-7 MMA -> D smem; warps 8-11 load next tile
//   phase B: all 12 warps, warp-per-edge coalesced epilogue -> g_a
// ============================================================
__device__ __forceinline__ void load_tile(uint32_t* eb, int* idx,
                                          const float* __restrict__ ea,
                                          int tile, int tl) {
    idx[tl]       = g_row[tile * 128 + tl];
    idx[128 + tl] = g_col[tile * 128 + tl];
    int rbase = tl >> 2, cbase = tl & 3;
#pragma unroll
    for (int i = 0; i < 4; i++) {
        int row = rbase + 32 * i;
        const float4* src = (const float4*)(ea + ((size_t)tile * 128 + row) * HID);
        uint32_t* drow = eb + row * EB_STRIDE;
#pragma unroll
        for (int j = 0; j < 4; j++) {
            int kb = cbase + 4 * j;               // k-block of 8 floats
            float4 v0 = src[kb * 2];
            float4 v1 = src[kb * 2 + 1];
            uint4 o0, o1;                          // pair-permute (k, k+4)
            o0.x = f2tf32(v0.x); o0.y = f2tf32(v1.x);
            o0.z = f2tf32(v0.y); o0.w = f2tf32(v1.y);
            o1.x = f2tf32(v0.z); o1.y = f2tf32(v1.z);
            o1.z = f2tf32(v0.w); o1.w = f2tf32(v1.w);
            *(uint4*)(drow + kb * 8)     = o0;
            *(uint4*)(drow + kb * 8 + 4) = o1;
        }
    }
}

__global__ void __launch_bounds__(384, 1) edge_mma(const float* __restrict__ ea,
                                                   const float* __restrict__ W1,
                                                   const float* __restrict__ b1,
                                                   const float* __restrict__ W2,
                                                   const float* __restrict__ b2) {
    extern __shared__ char sm[];
    uint32_t* eb0  = (uint32_t*)sm;                  // 71680 B
    uint32_t* eb1  = (uint32_t*)(sm + 71680);        // 71680 B
    float*    sD   = (float*)(sm + 143360);          // 128*132*4 = 67584 B
    int*      idx0 = (int*)(sm + 210944);            // 1024 B
    int*      idx1 = (int*)(sm + 211968);            // 1024 B
    float*    b1s  = (float*)(sm + 212992);          // 512 B
    float*    w2s  = (float*)(sm + 213504);          // 512 B

    int tid = threadIdx.x, wid = tid >> 5, lane = tid & 31;
    int tg = lane >> 2, tk = lane & 3;               // mma groupID / thread-in-group
    int bid = blockIdx.x;
    float b2v = b2[0];

    if (tid < 128) { b1s[tid] = b1[tid]; w2s[tid] = W2[tid]; }

    // A fragments: Wc^T slab for this warp (compute warps), once per kernel
    uint32_t afr[16][4];
    if (wid < 8) {
        int o0 = 16 * wid + tg;
#pragma unroll
        for (int K8 = 0; K8 < 16; K8++) {
            int kb = 2 * HID + K8 * 8;
            afr[K8][0] = f2tf32(W1[(kb + tk) * HID + o0]);
            afr[K8][1] = f2tf32(W1[(kb + tk) * HID + o0 + 8]);
            afr[K8][2] = f2tf32(W1[(kb + tk + 4) * HID + o0]);
            afr[K8][3] = f2tf32(W1[(kb + tk + 4) * HID + o0 + 8]);
        }
    } else {
        load_tile(eb0, idx0, ea, bid, tid - 256);
    }
    __syncthreads();

    int it = 0;
    for (int tile = bid; tile < NTILE; tile += GRID_TC, it++) {
        int p = it & 1;
        uint32_t* ebc = p ? eb1 : eb0;
        int*      idc = p ? idx1 : idx0;

        // ---- phase A: MMA -> sD (warps 0-7); load next tile (warps 8-11)
        if (wid < 8) {
            int o0 = 16 * wid + tg, o1 = o0 + 8;
#pragma unroll
            for (int slab = 0; slab < 2; slab++) {
                float c[8][4];
#pragma unroll
                for (int g = 0; g < 8; g++) { c[g][0]=0.f; c[g][1]=0.f; c[g][2]=0.f; c[g][3]=0.f; }
                const uint32_t* ebp = ebc + slab * 64 * EB_STRIDE;
#pragma unroll
                for (int K8 = 0; K8 < 16; K8++) {
#pragma unroll
                    for (int g = 0; g < 8; g++) {
                        uint2 b = *(const uint2*)(ebp + (g * 8 + tg) * EB_STRIDE + K8 * 8 + 2 * tk);
                        mma_tf(c[g], afr[K8], b.x, b.y);
                    }
                }
#pragma unroll
                for (int g = 0; g < 8; g++) {
                    int el = slab * 64 + g * 8 + 2 * tk;
                    sD[el * D_STRIDE + o0]       = c[g][0];
                    sD[(el + 1) * D_STRIDE + o0] = c[g][1];
                    sD[el * D_STRIDE + o1]       = c[g][2];
                    sD[(el + 1) * D_STRIDE + o1] = c[g][3];
                }
            }
        } else {
            int nt = tile + GRID_TC;
            if (nt < NTILE)
                load_tile(p ? eb0 : eb1, p ? idx0 : idx1, ea, nt, tid - 256);
        }
        __syncthreads();

        // ---- phase B: all warps, warp-per-edge coalesced epilogue
        for (int e = wid; e < 128; e += 12) {
            int row = idc[e], col = idc[128 + e];
            float4 d   = *(float4*)&sD[e * D_STRIDE + 4 * lane];
            float4 ha  = *(const float4*)&g_Ha[(size_t)row * HID + 4 * lane];
            float4 hb  = *(const float4*)&g_Hb[(size_t)col * HID + 4 * lane];
            float4 b1v = *(const float4*)&b1s[4 * lane];
            float4 w2v = *(const float4*)&w2s[4 * lane];
            float partial =
                elu(d.x + ha.x + hb.x + b1v.x) * w2v.x +
                elu(d.y + ha.y + hb.y + b1v.y) * w2v.y +
                elu(d.z + ha.z + hb.z + b1v.z) * w2v.z +
                elu(d.w + ha.w + hb.w + b1v.w) * w2v.w;
#pragma unroll
            for (int off = 16; off; off >>= 1)
                partial += __shfl_xor_sync(0xffffffffu, partial, off);
            if (lane == 0) {
                float a = partial + b2v;
                g_a[tile * 128 + e] = a > 0.f ? a : 0.2f * a;
            }
        }
        __syncthreads();
    }
}

// ============================================================
// Kernels 3/4: deterministic two-stage online logsumexp
// ============================================================
__device__ __forceinline__ void merge_ms(float& m, float& s, float m2, float s2) {
    float mn = fmaxf(m, m2);
    s = s * __expf(m - mn) + s2 * __expf(m2 - mn);
    m = mn;
}

__global__ void softmax_part() {
    int gtid = blockIdx.x * 256 + threadIdx.x;
    float m = -1e30f, s = 0.f;
    for (int i = gtid; i < NEDGE; i += 256 * 256) {
        float v = g_a[i];
        if (v > m) { s = s * __expf(m - v) + 1.f; m = v; }
        else       { s += __expf(v - m); }
    }
    __shared__ float sm_[256], ss_[256];
    sm_[threadIdx.x] = m; ss_[threadIdx.x] = s;
    __syncthreads();
    for (int off = 128; off; off >>= 1) {
        if (threadIdx.x < off) {
            float mm = sm_[threadIdx.x], ssv = ss_[threadIdx.x];
            merge_ms(mm, ssv, sm_[threadIdx.x + off], ss_[threadIdx.x + off]);
            sm_[threadIdx.x] = mm; ss_[threadIdx.x] = ssv;
        }
        __syncthreads();
    }
    if (threadIdx.x == 0) { g_pm[blockIdx.x] = sm_[0]; g_ps[blockIdx.x] = ss_[0]; }
}

__global__ void softmax_final() {
    int t = threadIdx.x;
    __shared__ float sm_[256], ss_[256];
    sm_[t] = g_pm[t]; ss_[t] = g_ps[t];
    __syncthreads();
    for (int off = 128; off; off >>= 1) {
        if (t < off) {
            float mm = sm_[t], ssv = ss_[t];
            merge_ms(mm, ssv, sm_[t + off], ss_[t + off]);
            sm_[t] = mm; ss_[t] = ssv;
        }
        __syncthreads();
    }
    if (t == 0) { g_stats[0] = sm_[0]; g_stats[1] = 1.f / ss_[0]; }
}

// ============================================================
// Kernel 5: scatter  out[row] += alpha_e * h[col]   (red.v4.f32)
// ============================================================
__global__ void __launch_bounds__(256) scatter(const float* __restrict__ h,
                                               float* __restrict__ out) {
    int gw = (blockIdx.x * 256 + threadIdx.x) >> 5;
    int l = threadIdx.x & 31;
    float m = g_stats[0], inv = g_stats[1];
    int e0 = gw * 4;
#pragma unroll
    for (int e = 0; e < 4; e++) {
        int ed = e0 + e;
        if (ed >= NEDGE) return;
        float alpha = __expf(g_a[ed] - m) * inv;
        int row = g_row[ed];
        int col = g_col[ed];
        float4 hv = *(const float4*)&h[(size_t)col * HID + 4 * l];
        float* dst = &out[(size_t)row * HID + 4 * l];
        asm volatile("red.global.add.v4.f32 [%0], {%1, %2, %3, %4};"
                     :: "l"(dst), "f"(alpha * hv.x), "f"(alpha * hv.y),
                        "f"(alpha * hv.z), "f"(alpha * hv.w)
                     : "memory");
    }
}

// ============================================================
extern "C" void kernel_launch(void* const* d_in, const int* in_sizes, int n_in,
                              void* d_out, int out_size) {
    const float* h  = (const float*)d_in[0];
    const void*  ei = (const void*)d_in[1];
    const float* ea = (const float*)d_in[2];
    const float* W1 = (const float*)d_in[3];
    const float* b1 = (const float*)d_in[4];
    const float* W2 = (const float*)d_in[5];
    const float* b2 = (const float*)d_in[6];
    float* out = (float*)d_out;

    cudaFuncSetAttribute(node_gemm, cudaFuncAttributeMaxDynamicSharedMemorySize, 147456);
    cudaFuncSetAttribute(edge_mma,  cudaFuncAttributeMaxDynamicSharedMemorySize, 214016);

    detect<<<1, 32>>>((const int*)ei);
    convert<<<(NEDGE + 255) / 256, 256>>>(ei);
    node_gemm<<<1563, 256, 147456>>>(h, W1);
    edge_mma<<<GRID_TC, 384, 214016>>>(ea, W1, b1, W2, b2);
    softmax_part<<<256, 256>>>();
    softmax_final<<<1, 256>>>();
    cudaMemsetAsync(d_out, 0, (size_t)out_size * sizeof(float));
    scatter<<<25000, 256>>>(h, out);
}

// round 7
// speedup vs baseline: 1.7356x; 1.0291x over previous
#include <cuda_runtime.h>
#include <cstdint>

#define HID   128
#define NEDGE 800000
#define NNODE 50000
#define NTILE 6250          // NEDGE / 128
#define GRID_E 444          // 3 CTAs/SM * 148 SMs
#define EB_STRIDE 140       // words per edge row

// ---- scratch (static __device__ arrays; allocation-free) ----
__device__ float g_Ha[NNODE * HID];
__device__ float g_Hb[NNODE * HID];
__device__ float g_a[NEDGE];
__device__ int   g_row[NEDGE];
__device__ int   g_col[NEDGE];
__device__ int   g_is64;
__device__ float g_pm[256];
__device__ float g_ps[256];
__device__ float g_stats[2];

// ---- helpers ----
__device__ __forceinline__ uint32_t f2tf32(float x) {
    uint32_t u;
    asm("cvt.rna.tf32.f32 %0, %1;" : "=r"(u) : "f"(x));
    return u;
}
__device__ __forceinline__ void mma_tf(float* c, const uint32_t* a, uint32_t b0, uint32_t b1) {
    asm volatile(
        "mma.sync.aligned.m16n8k8.row.col.f32.tf32.tf32.f32 "
        "{%0,%1,%2,%3}, {%4,%5,%6,%7}, {%8,%9}, {%0,%1,%2,%3};"
        : "+f"(c[0]), "+f"(c[1]), "+f"(c[2]), "+f"(c[3])
        : "r"(a[0]), "r"(a[1]), "r"(a[2]), "r"(a[3]), "r"(b0), "r"(b1));
}
__device__ __forceinline__ float elu(float x) {
    return x > 0.f ? x : (__expf(x) - 1.f);
}

// ---- packed f32x2 helpers for the node GEMM ----
__device__ __forceinline__ unsigned long long pk(float x, float y) {
    unsigned long long r;
    asm("mov.b64 %0, {%1, %2};" : "=l"(r) : "f"(x), "f"(y));
    return r;
}
__device__ __forceinline__ unsigned long long pk1(float x) { return pk(x, x); }
__device__ __forceinline__ void fma2(unsigned long long& d, unsigned long long a, unsigned long long b) {
    asm("fma.rn.f32x2 %0, %1, %2, %0;" : "+l"(d) : "l"(a), "l"(b));
}
__device__ __forceinline__ float2 upk(unsigned long long v) {
    float2 r;
    asm("mov.b64 {%0, %1}, %2;" : "=f"(r.x), "=f"(r.y) : "l"(v));
    return r;
}

// ============================================================
// Kernel 0a/0b: edge_index dtype detect + convert
// ============================================================
__global__ void detect(const int* __restrict__ ei32) {
    if (threadIdx.x == 0 && blockIdx.x == 0) {
        int orv = 0;
        for (int i = 0; i < 64; i++) orv |= ei32[2 * i + 1];
        g_is64 = (orv == 0) ? 1 : 0;
    }
}
__global__ void __launch_bounds__(256) convert(const void* __restrict__ eiraw) {
    int e = blockIdx.x * 256 + threadIdx.x;
    if (e >= NEDGE) return;
    int row, col;
    if (g_is64) {
        const long long* p = (const long long*)eiraw;
        row = (int)p[e]; col = (int)p[NEDGE + e];
    } else {
        const int* p = (const int*)eiraw;
        row = p[e]; col = p[NEDGE + e];
    }
    g_row[e] = min(max(row, 0), NNODE - 1);
    g_col[e] = min(max(col, 0), NNODE - 1);
}

// ============================================================
// Kernel 1: node GEMM  Ha = h@Wa, Hb = h@Wb  (FFMA2, unchanged)
// ============================================================
__global__ void __launch_bounds__(256, 1) node_gemm(const float* __restrict__ h,
                                                    const float* __restrict__ W1) {
    extern __shared__ char smraw[];
    unsigned long long* wab = (unsigned long long*)smraw;
    float* hst = (float*)(smraw + 131072);

    int tid = threadIdx.x;
    for (int idx = tid; idx < 128 * 128; idx += 256) {
        int k = idx >> 7, p = idx & 127;
        const float* src = (p < 64) ? &W1[k * HID + 2 * p]
                                    : &W1[(HID + k) * HID + 2 * (p - 64)];
        float2 v = *(const float2*)src;
        wab[idx] = pk(v.x, v.y);
    }
    __syncthreads();

    int w = tid >> 5, l = tid & 31;
    int group = blockIdx.x * 8 + w;
    if (group * 4 >= NNODE) return;
    int n0 = group * 4;

    float* hw = hst + w * 4 * HID;
#pragma unroll
    for (int e = 0; e < 4; e++) {
        float4 v = *(const float4*)&h[(size_t)(n0 + e) * HID + 4 * l];
        *(float4*)&hw[e * HID + 4 * l] = v;
    }
    __syncwarp();

    unsigned long long acc[4][4];
#pragma unroll
    for (int e = 0; e < 4; e++)
#pragma unroll
        for (int j = 0; j < 4; j++) acc[e][j] = 0ULL;

    for (int k = 0; k < HID; k += 2) {
        unsigned long long w0[4], w1[4];
#pragma unroll
        for (int j = 0; j < 4; j++) {
            w0[j] = wab[k * 128 + l + 32 * j];
            w1[j] = wab[(k + 1) * 128 + l + 32 * j];
        }
#pragma unroll
        for (int e = 0; e < 4; e++) {
            float2 hv = *(float2*)&hw[e * HID + k];
            unsigned long long hx = pk1(hv.x), hy = pk1(hv.y);
#pragma unroll
            for (int j = 0; j < 4; j++) {
                fma2(acc[e][j], hx, w0[j]);
                fma2(acc[e][j], hy, w1[j]);
            }
        }
    }

#pragma unroll
    for (int e = 0; e < 4; e++)
#pragma unroll
        for (int j = 0; j < 4; j++) {
            int p = l + 32 * j;
            float2 v = upk(acc[e][j]);
            if (p < 64)
                *(float2*)&g_Ha[(size_t)(n0 + e) * HID + 2 * p] = v;
            else
                *(float2*)&g_Hb[(size_t)(n0 + e) * HID + 2 * (p - 64)] = v;
        }
}

// ============================================================
// Kernel 2: edge GEMM via mma.sync tf32 + coalesced epilogue
//   256 threads, 8 warps, NO warp specialization, 3 CTAs/SM.
//   Edge buffer is reused in-place as the D tile (slab-wise).
//   A fragments re-read from gmem W1 per K8 (L1-resident).
// ============================================================
__global__ void __launch_bounds__(256, 3) edge_mma(const float* __restrict__ ea,
                                                   const float* __restrict__ W1,
                                                   const float* __restrict__ b1,
                                                   const float* __restrict__ W2,
                                                   const float* __restrict__ b2) {
    extern __shared__ char sm[];
    uint32_t* eb  = (uint32_t*)sm;            // [128][140] tf32 tile, 71680 B
    float*    sD  = (float*)sm;               // alias: D tile after MMA
    int*      idx = (int*)(sm + 71680);       // 1024 B
    float*    b1s = (float*)(sm + 72704);     // 512 B
    float*    w2s = (float*)(sm + 73216);     // 512 B

    int tid = threadIdx.x, wid = tid >> 5, lane = tid & 31;
    int tg = lane >> 2, tk = lane & 3;
    int o0 = 16 * wid + tg, o1 = o0 + 8;
    float b2v = b2[0];

    if (tid < 128) { b1s[tid] = b1[tid]; w2s[tid] = W2[tid]; }

    for (int tile = blockIdx.x; tile < NTILE; tile += GRID_E) {
        // ---- load indices + edge tile (coalesced flat passes) ----
        int e_ = tid & 127;
        idx[tid] = (tid < 128) ? g_row[tile * 128 + e_] : g_col[tile * 128 + e_];
        const float4* src = (const float4*)(ea + (size_t)tile * 128 * HID);
#pragma unroll
        for (int pass = 0; pass < 8; pass++) {
            int flat8 = pass * 256 + tid;          // 8-float chunk id (0..2047)
            int r = flat8 >> 4, kb = flat8 & 15;
            float4 v0 = src[flat8 * 2];
            float4 v1 = src[flat8 * 2 + 1];
            uint4 q0, q1;                           // pair-permute (k, k+4)
            q0.x = f2tf32(v0.x); q0.y = f2tf32(v1.x);
            q0.z = f2tf32(v0.y); q0.w = f2tf32(v1.y);
            q1.x = f2tf32(v0.z); q1.y = f2tf32(v1.z);
            q1.z = f2tf32(v0.w); q1.w = f2tf32(v1.w);
            uint32_t* drow = eb + r * EB_STRIDE + kb * 8;
            *(uint4*)(drow)     = q0;
            *(uint4*)(drow + 4) = q1;
        }
        __syncthreads();

        // ---- MMA, slab-wise, D written in-place over consumed slab ----
#pragma unroll
        for (int slab = 0; slab < 2; slab++) {
            float c[8][4];
#pragma unroll
            for (int g = 0; g < 8; g++) { c[g][0]=0.f; c[g][1]=0.f; c[g][2]=0.f; c[g][3]=0.f; }
            const uint32_t* ebp = eb + slab * 64 * EB_STRIDE;
#pragma unroll
            for (int K8 = 0; K8 < 16; K8++) {
                const float* wrow = W1 + (size_t)(2 * HID + K8 * 8 + tk) * HID;
                uint32_t a[4];
                a[0] = f2tf32(wrow[o0]);
                a[1] = f2tf32(wrow[o1]);
                a[2] = f2tf32(wrow[4 * HID + o0]);
                a[3] = f2tf32(wrow[4 * HID + o1]);
#pragma unroll
                for (int g = 0; g < 8; g++) {
                    uint2 b = *(const uint2*)(ebp + (g * 8 + tg) * EB_STRIDE + K8 * 8 + 2 * tk);
                    mma_tf(c[g], a, b.x, b.y);
                }
            }
            __syncthreads();   // all warps done READING this slab
#pragma unroll
            for (int g = 0; g < 8; g++) {
                int el = slab * 64 + g * 8 + 2 * tk;
                sD[el * EB_STRIDE + o0]       = c[g][0];
                sD[(el + 1) * EB_STRIDE + o0] = c[g][1];
                sD[el * EB_STRIDE + o1]       = c[g][2];
                sD[(el + 1) * EB_STRIDE + o1] = c[g][3];
            }
        }
        __syncthreads();       // D tile complete & visible

        // ---- epilogue: warp-per-edge, fully coalesced ----
#pragma unroll 4
        for (int i = 0; i < 16; i++) {
            int e = wid * 16 + i;
            int row = idx[e], col = idx[128 + e];
            float4 d   = *(float4*)&sD[e * EB_STRIDE + 4 * lane];
            float4 ha  = *(const float4*)&g_Ha[(size_t)row * HID + 4 * lane];
            float4 hb  = *(const float4*)&g_Hb[(size_t)col * HID + 4 * lane];
            float4 b1v = *(const float4*)&b1s[4 * lane];
            float4 w2v = *(const float4*)&w2s[4 * lane];
            float partial =
                elu(d.x + ha.x + hb.x + b1v.x) * w2v.x +
                elu(d.y + ha.y + hb.y + b1v.y) * w2v.y +
                elu(d.z + ha.z + hb.z + b1v.z) * w2v.z +
                elu(d.w + ha.w + hb.w + b1v.w) * w2v.w;
#pragma unroll
            for (int off = 16; off; off >>= 1)
                partial += __shfl_xor_sync(0xffffffffu, partial, off);
            if (lane == 0) {
                float a = partial + b2v;
                g_a[tile * 128 + e] = a > 0.f ? a : 0.2f * a;
            }
        }
        __syncthreads();       // eb/sD free for next tile's load
    }
}

// ============================================================
// Kernels 3/4: deterministic two-stage online logsumexp
// ============================================================
__device__ __forceinline__ void merge_ms(float& m, float& s, float m2, float s2) {
    float mn = fmaxf(m, m2);
    s = s * __expf(m - mn) + s2 * __expf(m2 - mn);
    m = mn;
}

__global__ void softmax_part() {
    int gtid = blockIdx.x * 256 + threadIdx.x;
    float m = -1e30f, s = 0.f;
    for (int i = gtid; i < NEDGE; i += 256 * 256) {
        float v = g_a[i];
        if (v > m) { s = s * __expf(m - v) + 1.f; m = v; }
        else       { s += __expf(v - m); }
    }
    __shared__ float sm_[256], ss_[256];
    sm_[threadIdx.x] = m; ss_[threadIdx.x] = s;
    __syncthreads();
    for (int off = 128; off; off >>= 1) {
        if (threadIdx.x < off) {
            float mm = sm_[threadIdx.x], ssv = ss_[threadIdx.x];
            merge_ms(mm, ssv, sm_[threadIdx.x + off], ss_[threadIdx.x + off]);
            sm_[threadIdx.x] = mm; ss_[threadIdx.x] = ssv;
        }
        __syncthreads();
    }
    if (threadIdx.x == 0) { g_pm[blockIdx.x] = sm_[0]; g_ps[blockIdx.x] = ss_[0]; }
}

__global__ void softmax_final() {
    int t = threadIdx.x;
    __shared__ float sm_[256], ss_[256];
    sm_[t] = g_pm[t]; ss_[t] = g_ps[t];
    __syncthreads();
    for (int off = 128; off; off >>= 1) {
        if (t < off) {
            float mm = sm_[t], ssv = ss_[t];
            merge_ms(mm, ssv, sm_[t + off], ss_[t + off]);
            sm_[t] = mm; ss_[t] = ssv;
        }
        __syncthreads();
    }
    if (t == 0) { g_stats[0] = sm_[0]; g_stats[1] = 1.f / ss_[0]; }
}

// ============================================================
// Kernel 5: scatter  out[row] += alpha_e * h[col]   (red.v4.f32)
// ============================================================
__global__ void __launch_bounds__(256) scatter(const float* __restrict__ h,
                                               float* __restrict__ out) {
    int gw = (blockIdx.x * 256 + threadIdx.x) >> 5;
    int l = threadIdx.x & 31;
    float m = g_stats[0], inv = g_stats[1];
    int e0 = gw * 4;
#pragma unroll
    for (int e = 0; e < 4; e++) {
        int ed = e0 + e;
        if (ed >= NEDGE) return;
        float alpha = __expf(g_a[ed] - m) * inv;
        int row = g_row[ed];
        int col = g_col[ed];
        float4 hv = *(const float4*)&h[(size_t)col * HID + 4 * l];
        float* dst = &out[(size_t)row * HID + 4 * l];
        asm volatile("red.global.add.v4.f32 [%0], {%1, %2, %3, %4};"
                     :: "l"(dst), "f"(alpha * hv.x), "f"(alpha * hv.y),
                        "f"(alpha * hv.z), "f"(alpha * hv.w)
                     : "memory");
    }
}

// ============================================================
extern "C" void kernel_launch(void* const* d_in, const int* in_sizes, int n_in,
                              void* d_out, int out_size) {
    const float* h  = (const float*)d_in[0];
    const void*  ei = (const void*)d_in[1];
    const float* ea = (const float*)d_in[2];
    const float* W1 = (const float*)d_in[3];
    const float* b1 = (const float*)d_in[4];
    const float* W2 = (const float*)d_in[5];
    const float* b2 = (const float*)d_in[6];
    float* out = (float*)d_out;

    cudaFuncSetAttribute(node_gemm, cudaFuncAttributeMaxDynamicSharedMemorySize, 147456);
    cudaFuncSetAttribute(edge_mma,  cudaFuncAttributeMaxDynamicSharedMemorySize, 73728);

    detect<<<1, 32>>>((const int*)ei);
    convert<<<(NEDGE + 255) / 256, 256>>>(ei);
    node_gemm<<<1563, 256, 147456>>>(h, W1);
    edge_mma<<<GRID_E, 256, 73728>>>(ea, W1, b1, W2, b2);
    softmax_part<<<256, 256>>>();
    softmax_final<<<1, 256>>>();
    cudaMemsetAsync(d_out, 0, (size_t)out_size * sizeof(float));
    scatter<<<25000, 256>>>(h, out);
}

// round 10
// speedup vs baseline: 2.5528x; 1.4709x over previous
#include <cuda_runtime.h>
#include <cstdint>

#define HID   128
#define NEDGE 800000
#define NNODE 50000
#define NTILE 6250          // NEDGE / 128
#define GRID_E 444          // 3 CTAs/SM * 148 SMs
#define EBS 72              // bf16x2 words per edge row (conflict-free LDS.64)
#define DS  132             // sD stride in floats (>=128 dims + conflict-free pad)

// ---- scratch (static __device__ arrays; allocation-free) ----
__device__ float g_Ha[NNODE * HID];
__device__ float g_Hb[NNODE * HID];
__device__ float g_a[NEDGE];
__device__ int   g_row[NEDGE];
__device__ int   g_col[NEDGE];
__device__ int   g_is64;
__device__ float g_pm[256];
__device__ float g_ps[256];
__device__ float g_stats[2];
__device__ uint4 g_Af[64 * 32];    // pre-packed bf16 A fragments [wid][K16][lane]

// ---- helpers ----
__device__ __forceinline__ uint32_t pk_bf(float lo, float hi) {
    uint32_t r;   // cvt.bf16x2: first src -> upper half
    asm("cvt.rn.bf16x2.f32 %0, %1, %2;" : "=r"(r) : "f"(hi), "f"(lo));
    return r;
}
__device__ __forceinline__ void mma_bf(float* c, const uint4& a, uint32_t b0, uint32_t b1) {
    asm volatile(
        "mma.sync.aligned.m16n8k16.row.col.f32.bf16.bf16.f32 "
        "{%0,%1,%2,%3}, {%4,%5,%6,%7}, {%8,%9}, {%0,%1,%2,%3};"
        : "+f"(c[0]), "+f"(c[1]), "+f"(c[2]), "+f"(c[3])
        : "r"(a.x), "r"(a.y), "r"(a.z), "r"(a.w), "r"(b0), "r"(b1));
}
__device__ __forceinline__ float elu(float x) {
    return x > 0.f ? x : (__expf(x) - 1.f);
}

// ---- packed f32x2 helpers for the node GEMM ----
__device__ __forceinline__ unsigned long long pk(float x, float y) {
    unsigned long long r;
    asm("mov.b64 %0, {%1, %2};" : "=l"(r) : "f"(x), "f"(y));
    return r;
}
__device__ __forceinline__ unsigned long long pk1(float x) { return pk(x, x); }
__device__ __forceinline__ void fma2(unsigned long long& d, unsigned long long a, unsigned long long b) {
    asm("fma.rn.f32x2 %0, %1, %2, %0;" : "+l"(d) : "l"(a), "l"(b));
}
__device__ __forceinline__ float2 upk(unsigned long long v) {
    float2 r;
    asm("mov.b64 {%0, %1}, %2;" : "=f"(r.x), "=f"(r.y) : "l"(v));
    return r;
}

// ============================================================
// Kernel 0a/0b: edge_index dtype detect + convert
// ============================================================
__global__ void detect(const int* __restrict__ ei32) {
    if (threadIdx.x == 0 && blockIdx.x == 0) {
        int orv = 0;
        for (int i = 0; i < 64; i++) orv |= ei32[2 * i + 1];
        g_is64 = (orv == 0) ? 1 : 0;
    }
}
__global__ void __launch_bounds__(256) convert(const void* __restrict__ eiraw) {
    int e = blockIdx.x * 256 + threadIdx.x;
    if (e >= NEDGE) return;
    int row, col;
    if (g_is64) {
        const long long* p = (const long long*)eiraw;
        row = (int)p[e]; col = (int)p[NEDGE + e];
    } else {
        const int* p = (const int*)eiraw;
        row = p[e]; col = p[NEDGE + e];
    }
    g_row[e] = min(max(row, 0), NNODE - 1);
    g_col[e] = min(max(col, 0), NNODE - 1);
}

// ============================================================
// Kernel 0c: pre-pack Wc into bf16 A-fragments (one-time, 32KB)
// ============================================================
__global__ void __launch_bounds__(256) prep_afrag(const float* __restrict__ W1) {
    int t = blockIdx.x * 256 + threadIdx.x;   // 0..2047
    int lane = t & 31, K16 = (t >> 5) & 7, wid = t >> 8;
    int tg = lane >> 2, tk = lane & 3;
    int o0 = 16 * wid + tg;
    int kb = K16 * 16 + 2 * tk;
    const float* Wc = W1 + 2 * HID * HID;
    uint4 r;
    r.x = pk_bf(Wc[kb * HID + o0],           Wc[(kb + 1) * HID + o0]);
    r.y = pk_bf(Wc[kb * HID + o0 + 8],       Wc[(kb + 1) * HID + o0 + 8]);
    r.z = pk_bf(Wc[(kb + 8) * HID + o0],     Wc[(kb + 9) * HID + o0]);
    r.w = pk_bf(Wc[(kb + 8) * HID + o0 + 8], Wc[(kb + 9) * HID + o0 + 8]);
    g_Af[t] = r;
}

// ============================================================
// Kernel 1: node GEMM  Ha = h@Wa, Hb = h@Wb  (FFMA2, unchanged)
// ============================================================
__global__ void __launch_bounds__(256, 1) node_gemm(const float* __restrict__ h,
                                                    const float* __restrict__ W1) {
    extern __shared__ char smraw[];
    unsigned long long* wab = (unsigned long long*)smraw;
    float* hst = (float*)(smraw + 131072);

    int tid = threadIdx.x;
    for (int idx = tid; idx < 128 * 128; idx += 256) {
        int k = idx >> 7, p = idx & 127;
        const float* src = (p < 64) ? &W1[k * HID + 2 * p]
                                    : &W1[(HID + k) * HID + 2 * (p - 64)];
        float2 v = *(const float2*)src;
        wab[idx] = pk(v.x, v.y);
    }
    __syncthreads();

    int w = tid >> 5, l = tid & 31;
    int group = blockIdx.x * 8 + w;
    if (group * 4 >= NNODE) return;
    int n0 = group * 4;

    float* hw = hst + w * 4 * HID;
#pragma unroll
    for (int e = 0; e < 4; e++) {
        float4 v = *(const float4*)&h[(size_t)(n0 + e) * HID + 4 * l];
        *(float4*)&hw[e * HID + 4 * l] = v;
    }
    __syncwarp();

    unsigned long long acc[4][4];
#pragma unroll
    for (int e = 0; e < 4; e++)
#pragma unroll
        for (int j = 0; j < 4; j++) acc[e][j] = 0ULL;

    for (int k = 0; k < HID; k += 2) {
        unsigned long long w0[4], w1[4];
#pragma unroll
        for (int j = 0; j < 4; j++) {
            w0[j] = wab[k * 128 + l + 32 * j];
            w1[j] = wab[(k + 1) * 128 + l + 32 * j];
        }
#pragma unroll
        for (int e = 0; e < 4; e++) {
            float2 hv = *(float2*)&hw[e * HID + k];
            unsigned long long hx = pk1(hv.x), hy = pk1(hv.y);
#pragma unroll
            for (int j = 0; j < 4; j++) {
                fma2(acc[e][j], hx, w0[j]);
                fma2(acc[e][j], hy, w1[j]);
            }
        }
    }

#pragma unroll
    for (int e = 0; e < 4; e++)
#pragma unroll
        for (int j = 0; j < 4; j++) {
            int p = l + 32 * j;
            float2 v = upk(acc[e][j]);
            if (p < 64)
                *(float2*)&g_Ha[(size_t)(n0 + e) * HID + 2 * p] = v;
            else
                *(float2*)&g_Hb[(size_t)(n0 + e) * HID + 2 * (p - 64)] = v;
        }
}

// ============================================================
// Kernel 2: edge GEMM via mma.sync bf16 m16n8k16 + coalesced epilogue
//   256 threads, 8 warps, 3 CTAs/SM. Slab-wise D buffer (stride 132).
//   smem: eb 36864 | sD 33792 | idx 1024 | b1s 512 | w2s 512 = 72704
// ============================================================
__global__ void __launch_bounds__(256, 3) edge_mma(const float* __restrict__ ea,
                                                   const float* __restrict__ b1,
                                                   const float* __restrict__ W2,
                                                   const float* __restrict__ b2) {
    extern __shared__ char sm[];
    uint32_t* eb  = (uint32_t*)sm;             // [128][72] bf16x2 words
    float*    sD  = (float*)(sm + 36864);      // [64][132] fp32 (one slab)
    int*      idx = (int*)(sm + 70656);        // 1024 B
    float*    b1s = (float*)(sm + 71680);      // 512 B
    float*    w2s = (float*)(sm + 72192);      // 512 B

    int tid = threadIdx.x, wid = tid >> 5, lane = tid & 31;
    int tg = lane >> 2, tk = lane & 3;
    int o0 = 16 * wid + tg, o1 = o0 + 8;
    float b2v = b2[0];

    if (tid < 128) { b1s[tid] = b1[tid]; w2s[tid] = W2[tid]; }

    for (int tile = blockIdx.x; tile < NTILE; tile += GRID_E) {
        // ---- load indices + edge tile as permuted bf16 ----
        int e_ = tid & 127;
        idx[tid] = (tid < 128) ? g_row[tile * 128 + e_] : g_col[tile * 128 + e_];
        const float4* src = (const float4*)(ea + (size_t)tile * 128 * HID);
#pragma unroll
        for (int pass = 0; pass < 8; pass++) {
            int flat8 = pass * 256 + tid;          // 8-float chunk (0..2047)
            int r = flat8 >> 4, kb = flat8 & 15;
            float4 v0 = src[flat8 * 2];
            float4 v1 = src[flat8 * 2 + 1];
            // K16 block = 8 words stored order w0,w4,w1,w5,w2,w6,w3,w7
            uint32_t* dr = eb + r * EBS + (kb >> 1) * 8 + (kb & 1);
            dr[0] = pk_bf(v0.x, v0.y);
            dr[2] = pk_bf(v0.z, v0.w);
            dr[4] = pk_bf(v1.x, v1.y);
            dr[6] = pk_bf(v1.z, v1.w);
        }
        __syncthreads();

#pragma unroll
        for (int slab = 0; slab < 2; slab++) {
            float c[8][4];
#pragma unroll
            for (int g = 0; g < 8; g++) { c[g][0]=0.f; c[g][1]=0.f; c[g][2]=0.f; c[g][3]=0.f; }
            const uint32_t* ebp = eb + slab * 64 * EBS;
#pragma unroll
            for (int K16 = 0; K16 < 8; K16++) {
                uint4 af = g_Af[(wid * 8 + K16) * 32 + lane];
#pragma unroll
                for (int g = 0; g < 8; g++) {
                    uint2 b = *(const uint2*)(ebp + (g * 8 + tg) * EBS + K16 * 8 + 2 * tk);
                    mma_bf(c[g], af, b.x, b.y);
                }
            }
            // D -> sD (previous epilogue's sync guarantees sD is free)
#pragma unroll
            for (int g = 0; g < 8; g++) {
                int el = g * 8 + 2 * tk;
                sD[el * DS + o0]       = c[g][0];
                sD[(el + 1) * DS + o0] = c[g][1];
                sD[el * DS + o1]       = c[g][2];
                sD[(el + 1) * DS + o1] = c[g][3];
            }
            __syncthreads();

            // ---- epilogue: warp-per-edge, 8 edges/warp for this slab ----
#pragma unroll
            for (int i = 0; i < 8; i++) {
                int el = wid * 8 + i;
                int e = slab * 64 + el;
                int row = idx[e], col = idx[128 + e];
                float4 d   = *(float4*)&sD[el * DS + 4 * lane];
                float4 ha  = *(const float4*)&g_Ha[(size_t)row * HID + 4 * lane];
                float4 hb  = *(const float4*)&g_Hb[(size_t)col * HID + 4 * lane];
                float4 b1v = *(const float4*)&b1s[4 * lane];
                float4 w2v = *(const float4*)&w2s[4 * lane];
                float partial =
                    elu(d.x + ha.x + hb.x + b1v.x) * w2v.x +
                    elu(d.y + ha.y + hb.y + b1v.y) * w2v.y +
                    elu(d.z + ha.z + hb.z + b1v.z) * w2v.z +
                    elu(d.w + ha.w + hb.w + b1v.w) * w2v.w;
#pragma unroll
                for (int off = 16; off; off >>= 1)
                    partial += __shfl_xor_sync(0xffffffffu, partial, off);
                if (lane == 0) {
                    float a = partial + b2v;
                    g_a[tile * 128 + e] = a > 0.f ? a : 0.2f * a;
                }
            }
            __syncthreads();
        }
    }
}

// ============================================================
// Kernels 3/4: deterministic two-stage online logsumexp
// ============================================================
__device__ __forceinline__ void merge_ms(float& m, float& s, float m2, float s2) {
    float mn = fmaxf(m, m2);
    s = s * __expf(m - mn) + s2 * __expf(m2 - mn);
    m = mn;
}

__global__ void softmax_part() {
    int gtid = blockIdx.x * 256 + threadIdx.x;
    float m = -1e30f, s = 0.f;
    for (int i = gtid; i < NEDGE; i += 256 * 256) {
        float v = g_a[i];
        if (v > m) { s = s * __expf(m - v) + 1.f; m = v; }
        else       { s += __expf(v - m); }
    }
    __shared__ float sm_[256], ss_[256];
    sm_[threadIdx.x] = m; ss_[threadIdx.x] = s;
    __syncthreads();
    for (int off = 128; off; off >>= 1) {
        if (threadIdx.x < off) {
            float mm = sm_[threadIdx.x], ssv = ss_[threadIdx.x];
            merge_ms(mm, ssv, sm_[threadIdx.x + off], ss_[threadIdx.x + off]);
            sm_[threadIdx.x] = mm; ss_[threadIdx.x] = ssv;
        }
        __syncthreads();
    }
    if (threadIdx.x == 0) { g_pm[blockIdx.x] = sm_[0]; g_ps[blockIdx.x] = ss_[0]; }
}

__global__ void softmax_final() {
    int t = threadIdx.x;
    __shared__ float sm_[256], ss_[256];
    sm_[t] = g_pm[t]; ss_[t] = g_ps[t];
    __syncthreads();
    for (int off = 128; off; off >>= 1) {
        if (t < off) {
            float mm = sm_[t], ssv = ss_[t];
            merge_ms(mm, ssv, sm_[t + off], ss_[t + off]);
            sm_[t] = mm; ss_[t] = ssv;
        }
        __syncthreads();
    }
    if (t == 0) { g_stats[0] = sm_[0]; g_stats[1] = 1.f / ss_[0]; }
}

// ============================================================
// Kernel 5: scatter  out[row] += alpha_e * h[col]   (red.v4.f32)
// ============================================================
__global__ void __launch_bounds__(256) scatter(const float* __restrict__ h,
                                               float* __restrict__ out) {
    int gw = (blockIdx.x * 256 + threadIdx.x) >> 5;
    int l = threadIdx.x & 31;
    float m = g_stats[0], inv = g_stats[1];
    int e0 = gw * 4;
#pragma unroll
    for (int e = 0; e < 4; e++) {
        int ed = e0 + e;
        if (ed >= NEDGE) return;
        float alpha = __expf(g_a[ed] - m) * inv;
        int row = g_row[ed];
        int col = g_col[ed];
        float4 hv = *(const float4*)&h[(size_t)col * HID + 4 * l];
        float* dst = &out[(size_t)row * HID + 4 * l];
        asm volatile("red.global.add.v4.f32 [%0], {%1, %2, %3, %4};"
                     :: "l"(dst), "f"(alpha * hv.x), "f"(alpha * hv.y),
                        "f"(alpha * hv.z), "f"(alpha * hv.w)
                     : "memory");
    }
}

// ============================================================
extern "C" void kernel_launch(void* const* d_in, const int* in_sizes, int n_in,
                              void* d_out, int out_size) {
    const float* h  = (const float*)d_in[0];
    const void*  ei = (const void*)d_in[1];
    const float* ea = (const float*)d_in[2];
    const float* W1 = (const float*)d_in[3];
    const float* b1 = (const float*)d_in[4];
    const float* W2 = (const float*)d_in[5];
    const float* b2 = (const float*)d_in[6];
    float* out = (float*)d_out;

    cudaFuncSetAttribute(node_gemm, cudaFuncAttributeMaxDynamicSharedMemorySize, 147456);
    cudaFuncSetAttribute(edge_mma,  cudaFuncAttributeMaxDynamicSharedMemorySize, 72704);

    detect<<<1, 32>>>((const int*)ei);
    convert<<<(NEDGE + 255) / 256, 256>>>(ei);
    prep_afrag<<<8, 256>>>(W1);
    node_gemm<<<1563, 256, 147456>>>(h, W1);
    edge_mma<<<GRID_E, 256, 72704>>>(ea, b1, W2, b2);
    softmax_part<<<256, 256>>>();
    softmax_final<<<1, 256>>>();
    cudaMemsetAsync(d_out, 0, (size_t)out_size * sizeof(float));
    scatter<<<25000, 256>>>(h, out);
}

// round 11
// speedup vs baseline: 3.1123x; 1.2192x over previous
#include <cuda_runtime.h>
#include <cstdint>

#define HID   128
#define NEDGE 800000
#define NNODE 50000
#define NTILE 6250          // NEDGE / 128
#define NTILEN 391          // ceil(NNODE / 128)
#define GRID_E 444          // 3 CTAs/SM * 148 SMs
#define EBS 72              // bf16x2 words per edge row (conflict-free LDS.64)
#define DS  132             // sD stride in floats
#define HBS 140             // tf32 words per node row in node_mma (conflict-free)

// ---- scratch (static __device__ arrays; allocation-free) ----
__device__ float g_Ha[NNODE * HID];
__device__ float g_Hb[NNODE * HID];
__device__ float g_a[NEDGE];
__device__ int   g_row[NEDGE];
__device__ int   g_col[NEDGE];
__device__ int   g_is64;
__device__ float g_pm[256];
__device__ float g_ps[256];
__device__ float g_stats[2];
__device__ uint4 g_Af[64 * 32];        // bf16 A frags for edge_mma [wid][K16][lane]
__device__ uint4 g_Wab[2 * 8 * 16 * 32]; // tf32 A frags for node_mma [slice][wid][K8][lane]

// ---- helpers ----
__device__ __forceinline__ uint32_t pk_bf(float lo, float hi) {
    uint32_t r;   // cvt.bf16x2: first src -> upper half
    asm("cvt.rn.bf16x2.f32 %0, %1, %2;" : "=r"(r) : "f"(hi), "f"(lo));
    return r;
}
__device__ __forceinline__ uint32_t f2tf32(float x) {
    uint32_t u;
    asm("cvt.rna.tf32.f32 %0, %1;" : "=r"(u) : "f"(x));
    return u;
}
__device__ __forceinline__ void mma_bf(float* c, const uint4& a, uint32_t b0, uint32_t b1) {
    asm volatile(
        "mma.sync.aligned.m16n8k16.row.col.f32.bf16.bf16.f32 "
        "{%0,%1,%2,%3}, {%4,%5,%6,%7}, {%8,%9}, {%0,%1,%2,%3};"
        : "+f"(c[0]), "+f"(c[1]), "+f"(c[2]), "+f"(c[3])
        : "r"(a.x), "r"(a.y), "r"(a.z), "r"(a.w), "r"(b0), "r"(b1));
}
__device__ __forceinline__ void mma_tf(float* c, const uint4& a, uint32_t b0, uint32_t b1) {
    asm volatile(
        "mma.sync.aligned.m16n8k8.row.col.f32.tf32.tf32.f32 "
        "{%0,%1,%2,%3}, {%4,%5,%6,%7}, {%8,%9}, {%0,%1,%2,%3};"
        : "+f"(c[0]), "+f"(c[1]), "+f"(c[2]), "+f"(c[3])
        : "r"(a.x), "r"(a.y), "r"(a.z), "r"(a.w), "r"(b0), "r"(b1));
}
__device__ __forceinline__ float elu(float x) {
    return x > 0.f ? x : (__expf(x) - 1.f);
}

// ============================================================
// Kernel 0a/0b: edge_index dtype detect + convert
// ============================================================
__global__ void detect(const int* __restrict__ ei32) {
    if (threadIdx.x == 0 && blockIdx.x == 0) {
        int orv = 0;
        for (int i = 0; i < 64; i++) orv |= ei32[2 * i + 1];
        g_is64 = (orv == 0) ? 1 : 0;
    }
}
__global__ void __launch_bounds__(256) convert(const void* __restrict__ eiraw) {
    int e = blockIdx.x * 256 + threadIdx.x;
    if (e >= NEDGE) return;
    int row, col;
    if (g_is64) {
        const long long* p = (const long long*)eiraw;
        row = (int)p[e]; col = (int)p[NEDGE + e];
    } else {
        const int* p = (const int*)eiraw;
        row = p[e]; col = p[NEDGE + e];
    }
    g_row[e] = min(max(row, 0), NNODE - 1);
    g_col[e] = min(max(col, 0), NNODE - 1);
}

// ============================================================
// Kernel 0c: pre-pack Wc into bf16 A-fragments (edge_mma)
// ============================================================
__global__ void __launch_bounds__(256) prep_afrag(const float* __restrict__ W1) {
    int t = blockIdx.x * 256 + threadIdx.x;   // 0..2047
    int lane = t & 31, K16 = (t >> 5) & 7, wid = t >> 8;
    int tg = lane >> 2, tk = lane & 3;
    int o0 = 16 * wid + tg;
    int kb = K16 * 16 + 2 * tk;
    const float* Wc = W1 + 2 * HID * HID;
    uint4 r;
    r.x = pk_bf(Wc[kb * HID + o0],           Wc[(kb + 1) * HID + o0]);
    r.y = pk_bf(Wc[kb * HID + o0 + 8],       Wc[(kb + 1) * HID + o0 + 8]);
    r.z = pk_bf(Wc[(kb + 8) * HID + o0],     Wc[(kb + 9) * HID + o0]);
    r.w = pk_bf(Wc[(kb + 8) * HID + o0 + 8], Wc[(kb + 9) * HID + o0 + 8]);
    g_Af[t] = r;
}

// ============================================================
// Kernel 0d: pre-pack Wa|Wb into tf32 A-fragments (node_mma)
//   layout [slice][wid][K8][lane]; a = {(k+tk,o0),(k+tk,o0+8),(k+tk+4,o0),(k+tk+4,o0+8)}
// ============================================================
__global__ void __launch_bounds__(256) prep_wab(const float* __restrict__ W1) {
    int t = blockIdx.x * 256 + threadIdx.x;   // 0..8191
    int lane = t & 31, K8 = (t >> 5) & 15, wid = (t >> 9) & 7, s = t >> 12;
    int tg = lane >> 2, tk = lane & 3;
    int o0 = 16 * wid + tg;
    int kb = K8 * 8;
    const float* Wb_ = W1 + (size_t)s * HID * HID;   // s=0: Wa rows, s=1: Wb rows
    uint4 r;
    r.x = f2tf32(Wb_[(kb + tk) * HID + o0]);
    r.y = f2tf32(Wb_[(kb + tk) * HID + o0 + 8]);
    r.z = f2tf32(Wb_[(kb + tk + 4) * HID + o0]);
    r.w = f2tf32(Wb_[(kb + tk + 4) * HID + o0 + 8]);
    g_Wab[t] = r;
}

// ============================================================
// Kernel 1: node GEMM via mma.sync tf32  ->  Ha | Hb
//   one CTA per 128-node tile; 256 threads.
//   smem: h tile tf32 [128][140] = 71680 B.
// ============================================================
__global__ void __launch_bounds__(256, 2) node_mma(const float* __restrict__ h) {
    extern __shared__ uint32_t eb[];           // [128][HBS]
    int tid = threadIdx.x, wid = tid >> 5, lane = tid & 31;
    int tg = lane >> 2, tk = lane & 3;
    int o0 = 16 * wid + tg, o1 = o0 + 8;
    int nbase = blockIdx.x * 128;

    // load h tile as permuted tf32 (guard tail)
    const float4* src = (const float4*)(h + (size_t)nbase * HID);
#pragma unroll
    for (int pass = 0; pass < 8; pass++) {
        int flat8 = pass * 256 + tid;          // 8-float chunk (0..2047)
        int r = flat8 >> 4, kb = flat8 & 15;
        float4 v0 = make_float4(0.f, 0.f, 0.f, 0.f), v1 = v0;
        if (nbase + r < NNODE) {
            v0 = src[flat8 * 2];
            v1 = src[flat8 * 2 + 1];
        }
        uint4 q0, q1;                           // pair-permute (k, k+4)
        q0.x = f2tf32(v0.x); q0.y = f2tf32(v1.x);
        q0.z = f2tf32(v0.y); q0.w = f2tf32(v1.y);
        q1.x = f2tf32(v0.z); q1.y = f2tf32(v1.z);
        q1.z = f2tf32(v0.w); q1.w = f2tf32(v1.w);
        uint32_t* drow = eb + r * HBS + kb * 8;
        *(uint4*)(drow)     = q0;
        *(uint4*)(drow + 4) = q1;
    }
    __syncthreads();

#pragma unroll
    for (int slab = 0; slab < 2; slab++) {
        float c0[8][4], c1[8][4];
#pragma unroll
        for (int g = 0; g < 8; g++) {
            c0[g][0]=0.f; c0[g][1]=0.f; c0[g][2]=0.f; c0[g][3]=0.f;
            c1[g][0]=0.f; c1[g][1]=0.f; c1[g][2]=0.f; c1[g][3]=0.f;
        }
        const uint32_t* ebp = eb + slab * 64 * HBS;
#pragma unroll
        for (int K8 = 0; K8 < 16; K8++) {
            uint4 a0 = g_Wab[(wid * 16 + K8) * 32 + lane];          // slice 0 (Wa)
            uint4 a1 = g_Wab[4096 + (wid * 16 + K8) * 32 + lane];   // slice 1 (Wb)
#pragma unroll
            for (int g = 0; g < 8; g++) {
                uint2 b = *(const uint2*)(ebp + (g * 8 + tg) * HBS + K8 * 8 + 2 * tk);
                mma_tf(c0[g], a0, b.x, b.y);
                mma_tf(c1[g], a1, b.x, b.y);
            }
        }
#pragma unroll
        for (int g = 0; g < 8; g++) {
            int node = nbase + slab * 64 + g * 8 + 2 * tk;
            if (node < NNODE) {
                g_Ha[(size_t)node * HID + o0] = c0[g][0];
                g_Ha[(size_t)node * HID + o1] = c0[g][2];
                g_Hb[(size_t)node * HID + o0] = c1[g][0];
                g_Hb[(size_t)node * HID + o1] = c1[g][2];
            }
            if (node + 1 < NNODE) {
                g_Ha[(size_t)(node + 1) * HID + o0] = c0[g][1];
                g_Ha[(size_t)(node + 1) * HID + o1] = c0[g][3];
                g_Hb[(size_t)(node + 1) * HID + o0] = c1[g][1];
                g_Hb[(size_t)(node + 1) * HID + o1] = c1[g][3];
            }
        }
    }
}

// ============================================================
// Kernel 2: edge GEMM via mma.sync bf16 m16n8k16 + coalesced epilogue
//   (unchanged from round 10 pass)
// ============================================================
__global__ void __launch_bounds__(256, 3) edge_mma(const float* __restrict__ ea,
                                                   const float* __restrict__ b1,
                                                   const float* __restrict__ W2,
                                                   const float* __restrict__ b2) {
    extern __shared__ char sm[];
    uint32_t* eb  = (uint32_t*)sm;             // [128][72] bf16x2 words
    float*    sD  = (float*)(sm + 36864);      // [64][132] fp32 (one slab)
    int*      idx = (int*)(sm + 70656);        // 1024 B
    float*    b1s = (float*)(sm + 71680);      // 512 B
    float*    w2s = (float*)(sm + 72192);      // 512 B

    int tid = threadIdx.x, wid = tid >> 5, lane = tid & 31;
    int tg = lane >> 2, tk = lane & 3;
    int o0 = 16 * wid + tg, o1 = o0 + 8;
    float b2v = b2[0];

    if (tid < 128) { b1s[tid] = b1[tid]; w2s[tid] = W2[tid]; }

    for (int tile = blockIdx.x; tile < NTILE; tile += GRID_E) {
        int e_ = tid & 127;
        idx[tid] = (tid < 128) ? g_row[tile * 128 + e_] : g_col[tile * 128 + e_];
        const float4* src = (const float4*)(ea + (size_t)tile * 128 * HID);
#pragma unroll
        for (int pass = 0; pass < 8; pass++) {
            int flat8 = pass * 256 + tid;
            int r = flat8 >> 4, kb = flat8 & 15;
            float4 v0 = src[flat8 * 2];
            float4 v1 = src[flat8 * 2 + 1];
            uint32_t* dr = eb + r * EBS + (kb >> 1) * 8 + (kb & 1);
            dr[0] = pk_bf(v0.x, v0.y);
            dr[2] = pk_bf(v0.z, v0.w);
            dr[4] = pk_bf(v1.x, v1.y);
            dr[6] = pk_bf(v1.z, v1.w);
        }
        __syncthreads();

#pragma unroll
        for (int slab = 0; slab < 2; slab++) {
            float c[8][4];
#pragma unroll
            for (int g = 0; g < 8; g++) { c[g][0]=0.f; c[g][1]=0.f; c[g][2]=0.f; c[g][3]=0.f; }
            const uint32_t* ebp = eb + slab * 64 * EBS;
#pragma unroll
            for (int K16 = 0; K16 < 8; K16++) {
                uint4 af = g_Af[(wid * 8 + K16) * 32 + lane];
#pragma unroll
                for (int g = 0; g < 8; g++) {
                    uint2 b = *(const uint2*)(ebp + (g * 8 + tg) * EBS + K16 * 8 + 2 * tk);
                    mma_bf(c[g], af, b.x, b.y);
                }
            }
#pragma unroll
            for (int g = 0; g < 8; g++) {
                int el = g * 8 + 2 * tk;
                sD[el * DS + o0]       = c[g][0];
                sD[(el + 1) * DS + o0] = c[g][1];
                sD[el * DS + o1]       = c[g][2];
                sD[(el + 1) * DS + o1] = c[g][3];
            }
            __syncthreads();

#pragma unroll
            for (int i = 0; i < 8; i++) {
                int el = wid * 8 + i;
                int e = slab * 64 + el;
                int row = idx[e], col = idx[128 + e];
                float4 d   = *(float4*)&sD[el * DS + 4 * lane];
                float4 ha  = *(const float4*)&g_Ha[(size_t)row * HID + 4 * lane];
                float4 hb  = *(const float4*)&g_Hb[(size_t)col * HID + 4 * lane];
                float4 b1v = *(const float4*)&b1s[4 * lane];
                float4 w2v = *(const float4*)&w2s[4 * lane];
                float partial =
                    elu(d.x + ha.x + hb.x + b1v.x) * w2v.x +
                    elu(d.y + ha.y + hb.y + b1v.y) * w2v.y +
                    elu(d.z + ha.z + hb.z + b1v.z) * w2v.z +
                    elu(d.w + ha.w + hb.w + b1v.w) * w2v.w;
#pragma unroll
                for (int off = 16; off; off >>= 1)
                    partial += __shfl_xor_sync(0xffffffffu, partial, off);
                if (lane == 0) {
                    float a = partial + b2v;
                    g_a[tile * 128 + e] = a > 0.f ? a : 0.2f * a;
                }
            }
            __syncthreads();
        }
    }
}

// ============================================================
// Kernels 3/4: deterministic two-stage online logsumexp
// ============================================================
__device__ __forceinline__ void merge_ms(float& m, float& s, float m2, float s2) {
    float mn = fmaxf(m, m2);
    s = s * __expf(m - mn) + s2 * __expf(m2 - mn);
    m = mn;
}

__global__ void softmax_part() {
    int gtid = blockIdx.x * 256 + threadIdx.x;
    float m = -1e30f, s = 0.f;
    for (int i = gtid; i < NEDGE; i += 256 * 256) {
        float v = g_a[i];
        if (v > m) { s = s * __expf(m - v) + 1.f; m = v; }
        else       { s += __expf(v - m); }
    }
    __shared__ float sm_[256], ss_[256];
    sm_[threadIdx.x] = m; ss_[threadIdx.x] = s;
    __syncthreads();
    for (int off = 128; off; off >>= 1) {
        if (threadIdx.x < off) {
            float mm = sm_[threadIdx.x], ssv = ss_[threadIdx.x];
            merge_ms(mm, ssv, sm_[threadIdx.x + off], ss_[threadIdx.x + off]);
            sm_[threadIdx.x] = mm; ss_[threadIdx.x] = ssv;
        }
        __syncthreads();
    }
    if (threadIdx.x == 0) { g_pm[blockIdx.x] = sm_[0]; g_ps[blockIdx.x] = ss_[0]; }
}

__global__ void softmax_final() {
    int t = threadIdx.x;
    __shared__ float sm_[256], ss_[256];
    sm_[t] = g_pm[t]; ss_[t] = g_ps[t];
    __syncthreads();
    for (int off = 128; off; off >>= 1) {
        if (t < off) {
            float mm = sm_[t], ssv = ss_[t];
            merge_ms(mm, ssv, sm_[t + off], ss_[t + off]);
            sm_[t] = mm; ss_[t] = ssv;
        }
        __syncthreads();
    }
    if (t == 0) { g_stats[0] = sm_[0]; g_stats[1] = 1.f / ss_[0]; }
}

// ============================================================
// Kernel 5: scatter  out[row] += alpha_e * h[col]   (red.v4.f32)
// ============================================================
__global__ void __launch_bounds__(256) scatter(const float* __restrict__ h,
                                               float* __restrict__ out) {
    int gw = (blockIdx.x * 256 + threadIdx.x) >> 5;
    int l = threadIdx.x & 31;
    float m = g_stats[0], inv = g_stats[1];
    int e0 = gw * 4;
#pragma unroll
    for (int e = 0; e < 4; e++) {
        int ed = e0 + e;
        if (ed >= NEDGE) return;
        float alpha = __expf(g_a[ed] - m) * inv;
        int row = g_row[ed];
        int col = g_col[ed];
        float4 hv = *(const float4*)&h[(size_t)col * HID + 4 * l];
        float* dst = &out[(size_t)row * HID + 4 * l];
        asm volatile("red.global.add.v4.f32 [%0], {%1, %2, %3, %4};"
                     :: "l"(dst), "f"(alpha * hv.x), "f"(alpha * hv.y),
                        "f"(alpha * hv.z), "f"(alpha * hv.w)
                     : "memory");
    }
}

// ============================================================
extern "C" void kernel_launch(void* const* d_in, const int* in_sizes, int n_in,
                              void* d_out, int out_size) {
    const float* h  = (const float*)d_in[0];
    const void*  ei = (const void*)d_in[1];
    const float* ea = (const float*)d_in[2];
    const float* W1 = (const float*)d_in[3];
    const float* b1 = (const float*)d_in[4];
    const float* W2 = (const float*)d_in[5];
    const float* b2 = (const float*)d_in[6];
    float* out = (float*)d_out;

    cudaFuncSetAttribute(node_mma, cudaFuncAttributeMaxDynamicSharedMemorySize, 71680);
    cudaFuncSetAttribute(edge_mma, cudaFuncAttributeMaxDynamicSharedMemorySize, 72704);

    detect<<<1, 32>>>((const int*)ei);
    convert<<<(NEDGE + 255) / 256, 256>>>(ei);
    prep_afrag<<<8, 256>>>(W1);
    prep_wab<<<32, 256>>>(W1);
    node_mma<<<NTILEN, 256, 71680>>>(h);
    edge_mma<<<GRID_E, 256, 72704>>>(ea, b1, W2, b2);
    softmax_part<<<256, 256>>>();
    softmax_final<<<1, 256>>>();
    cudaMemsetAsync(d_out, 0, (size_t)out_size * sizeof(float));
    scatter<<<25000, 256>>>(h, out);
}